// round 12
// baseline (speedup 1.0000x reference)
#include <cuda_runtime.h>

// ---------------------------------------------------------------------------
// ClassifierHetero — live dataflow only (conv stack is dead code in reference):
//   hg[b] = [mean(h_comp|g=b), mean2(h_port|g=b), mean(h_net|g=b)]  -> [64,4]
//   out   = relu(relu(hg@Wc1+bc1)@Wc2+bc2)@Wc3+bc3                  -> [64,10]
//
// R9: fused single launch, repaired.
//  - launch_bounds(256,4): 64-reg budget (R7's (256,8)=32 regs re-rolled the
//    MLP loads into ~128 serial round trips — the regression).
//  - MLP Wc2 dot split-k by 2 across 256 threads: 64 unrolled loads/thread,
//    fits 64 regs, keeps ~30 loads in flight.
//  - Grid = 592 = 4 CTA/SM * 148 SMs exactly -> all blocks co-resident in one
//    wave (regs<=64, smem ~3KB): spin-wait provably deadlock-free.
//  - Reduce uses 128-elem warp windows (int4/float4): 4x fewer serial windows.
// All __device__ state returns to zero each replay (consume-and-reset).
// ---------------------------------------------------------------------------

#define NB    64            // graphs (MLP blocks)
#define NRED  528           // reduce blocks
#define NBLK  (NRED + NB)   // 592 = 4 * 148

__device__ float g_sum[4 * NB];  // [0]=comp, [1]=port.x, [2]=port.y, [3]=net
__device__ int   g_cnt[3 * NB];  // [0]=comp, [1]=port,   [2]=net
__device__ int   g_done;         // reduce-blocks-finished counter
__device__ int   g_ack;          // MLP-blocks-finished counter

__device__ __forceinline__ float warp_sum_f(float v) {
#pragma unroll
    for (int o = 16; o; o >>= 1) v += __shfl_xor_sync(0xffffffffu, v, o);
    return v;
}

__device__ __forceinline__ void l2_prefetch(const void* p) {
    asm volatile("prefetch.global.L2 [%0];" :: "l"(p));
}

__global__ void __launch_bounds__(256, 4)
hx_fused_kernel(const float* __restrict__ h_comp,
                const int*   __restrict__ gid_comp, int nc,
                const float* __restrict__ h_port,
                const int*   __restrict__ gid_port, int np,
                const float* __restrict__ h_net,
                const int*   __restrict__ gid_net,  int nn,
                const float* __restrict__ Wc1, const float* __restrict__ bc1,
                const float* __restrict__ Wc2, const float* __restrict__ bc2,
                const float* __restrict__ Wc3, const float* __restrict__ bc3,
                float* __restrict__ out) {
    // =====================================================================
    // Role: REDUCE (blocks NB..NBLK-1). 128-element windows per warp.
    // =====================================================================
    if (blockIdx.x >= NB) {
        __shared__ float s_sum[4 * NB];
        __shared__ int   s_cnt[3 * NB];
        for (int i = threadIdx.x; i < 4 * NB; i += blockDim.x) s_sum[i] = 0.0f;
        for (int i = threadIdx.x; i < 3 * NB; i += blockDim.x) s_cnt[i] = 0;
        __syncthreads();

        const int lane   = threadIdx.x & 31;
        const int rb     = blockIdx.x - NB;
        const int warp_g = (rb * blockDim.x + threadIdx.x) >> 5;
        const int nwarps = (NRED * blockDim.x) >> 5;

        const int wc_c = (nc + 127) >> 7;
        const int wc_p = (np + 127) >> 7;
        const int wc_n = (nn + 127) >> 7;
        const int wc_total = wc_c + wc_p + wc_n;

        for (int w = warp_g; w < wc_total; w += nwarps) {
            if (w < wc_c) {
                // ---- component: 1 column ----
                int base = w << 7;
                int idx  = base + lane * 4;
                if (base + 128 <= nc) {
                    int4   g4 = *reinterpret_cast<const int4*>(gid_comp + idx);
                    float4 v4 = *reinterpret_cast<const float4*>(h_comp + idx);
                    bool uni = (g4.x == g4.y) && (g4.x == g4.z) && (g4.x == g4.w);
                    int g0 = __shfl_sync(0xffffffffu, g4.x, 0);
                    uni = uni && (g4.x == g0);
                    if (__all_sync(0xffffffffu, uni)) {
                        float s = warp_sum_f((v4.x + v4.y) + (v4.z + v4.w));
                        if (lane == 0) {
                            atomicAdd(&s_sum[0 * NB + g0], s);
                            atomicAdd(&s_cnt[0 * NB + g0], 128);
                        }
                    } else {
                        int   ga[4] = {g4.x, g4.y, g4.z, g4.w};
                        float va[4] = {v4.x, v4.y, v4.z, v4.w};
#pragma unroll
                        for (int e = 0; e < 4; e++) {
                            atomicAdd(&s_sum[0 * NB + ga[e]], va[e]);
                            atomicAdd(&s_cnt[0 * NB + ga[e]], 1);
                        }
                    }
                } else {
#pragma unroll
                    for (int e = 0; e < 4; e++) {
                        int id = idx + e;
                        if (id < nc) {
                            int g = gid_comp[id];
                            atomicAdd(&s_sum[0 * NB + g], h_comp[id]);
                            atomicAdd(&s_cnt[0 * NB + g], 1);
                        }
                    }
                }
            } else if (w < wc_c + wc_p) {
                // ---- port: 2 columns ----
                int base = (w - wc_c) << 7;
                int idx  = base + lane * 4;
                if (base + 128 <= np) {
                    int4   g4 = *reinterpret_cast<const int4*>(gid_port + idx);
                    float4 lo = *reinterpret_cast<const float4*>(h_port + 2 * idx);
                    float4 hi = *reinterpret_cast<const float4*>(h_port + 2 * idx + 4);
                    bool uni = (g4.x == g4.y) && (g4.x == g4.z) && (g4.x == g4.w);
                    int g0 = __shfl_sync(0xffffffffu, g4.x, 0);
                    uni = uni && (g4.x == g0);
                    if (__all_sync(0xffffffffu, uni)) {
                        float sx = warp_sum_f((lo.x + lo.z) + (hi.x + hi.z));
                        float sy = warp_sum_f((lo.y + lo.w) + (hi.y + hi.w));
                        if (lane == 0) {
                            atomicAdd(&s_sum[1 * NB + g0], sx);
                            atomicAdd(&s_sum[2 * NB + g0], sy);
                            atomicAdd(&s_cnt[1 * NB + g0], 128);
                        }
                    } else {
                        int   ga[4] = {g4.x, g4.y, g4.z, g4.w};
                        float vx[4] = {lo.x, lo.z, hi.x, hi.z};
                        float vy[4] = {lo.y, lo.w, hi.y, hi.w};
#pragma unroll
                        for (int e = 0; e < 4; e++) {
                            atomicAdd(&s_sum[1 * NB + ga[e]], vx[e]);
                            atomicAdd(&s_sum[2 * NB + ga[e]], vy[e]);
                            atomicAdd(&s_cnt[1 * NB + ga[e]], 1);
                        }
                    }
                } else {
#pragma unroll
                    for (int e = 0; e < 4; e++) {
                        int id = idx + e;
                        if (id < np) {
                            int g = gid_port[id];
                            float2 v = reinterpret_cast<const float2*>(h_port)[id];
                            atomicAdd(&s_sum[1 * NB + g], v.x);
                            atomicAdd(&s_sum[2 * NB + g], v.y);
                            atomicAdd(&s_cnt[1 * NB + g], 1);
                        }
                    }
                }
            } else {
                // ---- net: 1 column ----
                int base = (w - wc_c - wc_p) << 7;
                int idx  = base + lane * 4;
                if (base + 128 <= nn) {
                    int4   g4 = *reinterpret_cast<const int4*>(gid_net + idx);
                    float4 v4 = *reinterpret_cast<const float4*>(h_net + idx);
                    bool uni = (g4.x == g4.y) && (g4.x == g4.z) && (g4.x == g4.w);
                    int g0 = __shfl_sync(0xffffffffu, g4.x, 0);
                    uni = uni && (g4.x == g0);
                    if (__all_sync(0xffffffffu, uni)) {
                        float s = warp_sum_f((v4.x + v4.y) + (v4.z + v4.w));
                        if (lane == 0) {
                            atomicAdd(&s_sum[3 * NB + g0], s);
                            atomicAdd(&s_cnt[2 * NB + g0], 128);
                        }
                    } else {
                        int   ga[4] = {g4.x, g4.y, g4.z, g4.w};
                        float va[4] = {v4.x, v4.y, v4.z, v4.w};
#pragma unroll
                        for (int e = 0; e < 4; e++) {
                            atomicAdd(&s_sum[3 * NB + ga[e]], va[e]);
                            atomicAdd(&s_cnt[2 * NB + ga[e]], 1);
                        }
                    }
                } else {
#pragma unroll
                    for (int e = 0; e < 4; e++) {
                        int id = idx + e;
                        if (id < nn) {
                            int g = gid_net[id];
                            atomicAdd(&s_sum[3 * NB + g], h_net[id]);
                            atomicAdd(&s_cnt[2 * NB + g], 1);
                        }
                    }
                }
            }
        }
        __syncthreads();

        for (int i = threadIdx.x; i < 4 * NB; i += blockDim.x)
            if (s_sum[i] != 0.0f) atomicAdd(&g_sum[i], s_sum[i]);
        for (int i = threadIdx.x; i < 3 * NB; i += blockDim.x)
            if (s_cnt[i] != 0) atomicAdd(&g_cnt[i], s_cnt[i]);
        __syncthreads();

        if (threadIdx.x == 0) {
            __threadfence();
            atomicAdd(&g_done, 1);
        }
        return;
    }

    // =====================================================================
    // Role: MLP (blocks 0..63, one graph row each; 256 threads)
    // =====================================================================
    const int b = blockIdx.x;
    const int t = threadIdx.x;
    const int j = t & 127;     // output index
    const int h = t >> 7;      // k-half for the Wc2 stage

    // --- Prefetch classifier weights into L2 (partitioned across blocks) ---
    if (t < 8)  l2_prefetch(Wc2 + (b * 8 + t) * 32);        // 64 blks * 8 = 512 lines
    if (t == 8 && b < 40) l2_prefetch(Wc3 + b * 32);        // 40 lines
    if (t == 9 && b < 16) l2_prefetch(Wc1 + b * 32);        // 16 lines
    if (b == 0 && t >= 10 && t < 14) {
        const float* bs[4] = {bc1, bc1 + 64, bc2, bc2 + 64};
        l2_prefetch(bs[t - 10]);
    }
    if (b == 0 && t == 14) l2_prefetch(bc3);

    // --- Wait for all reduce blocks ---
    if (t == 0) {
        while (atomicAdd(&g_done, 0) < NRED) __nanosleep(128);
        __threadfence();
    }
    __syncthreads();

    __shared__ float shg[4];
    __shared__ float sh1[128];
    __shared__ float s_part[256];
    __shared__ float sh2[128];

    if (t == 0) {
        float s0 = __ldcg(&g_sum[0 * NB + b]);
        float s1 = __ldcg(&g_sum[1 * NB + b]);
        float s2 = __ldcg(&g_sum[2 * NB + b]);
        float s3 = __ldcg(&g_sum[3 * NB + b]);
        float c0 = (float)__ldcg(&g_cnt[0 * NB + b]);
        float c1 = (float)__ldcg(&g_cnt[1 * NB + b]);
        float c2 = (float)__ldcg(&g_cnt[2 * NB + b]);
        shg[0] = s0 / fmaxf(c0, 1.0f);
        shg[1] = s1 / fmaxf(c1, 1.0f);
        shg[2] = s2 / fmaxf(c1, 1.0f);
        shg[3] = s3 / fmaxf(c2, 1.0f);
        g_sum[0 * NB + b] = 0.0f;
        g_sum[1 * NB + b] = 0.0f;
        g_sum[2 * NB + b] = 0.0f;
        g_sum[3 * NB + b] = 0.0f;
        g_cnt[0 * NB + b] = 0;
        g_cnt[1 * NB + b] = 0;
        g_cnt[2 * NB + b] = 0;
    }
    __syncthreads();

    // ---- h1 = relu(hg @ Wc1 + bc1) (threads 0..127) ----
    if (t < 128) {
        float v = shg[0] * Wc1[0 * 128 + j] + shg[1] * Wc1[1 * 128 + j] +
                  shg[2] * Wc1[2 * 128 + j] + shg[3] * Wc1[3 * 128 + j] + bc1[j];
        sh1[j] = fmaxf(v, 0.0f);
    }
    __syncthreads();

    // ---- h2 = relu(sh1 @ Wc2 + bc2): split-k by 2, 64 unrolled loads ----
    {
        const float* __restrict__ w2 = Wc2 + (h * 64) * 128 + j;
        const float* __restrict__ x1 = sh1 + h * 64;
        float a0 = 0.0f, a1 = 0.0f, a2 = 0.0f, a3 = 0.0f;
#pragma unroll
        for (int k = 0; k < 64; k += 4) {
            a0 = fmaf(x1[k + 0], w2[(k + 0) * 128], a0);
            a1 = fmaf(x1[k + 1], w2[(k + 1) * 128], a1);
            a2 = fmaf(x1[k + 2], w2[(k + 2) * 128], a2);
            a3 = fmaf(x1[k + 3], w2[(k + 3) * 128], a3);
        }
        s_part[t] = (a0 + a1) + (a2 + a3);
    }
    __syncthreads();
    if (t < 128)
        sh2[j] = fmaxf(s_part[j] + s_part[128 + j] + bc2[j], 0.0f);
    __syncthreads();

    // ---- out = sh2 @ Wc3 + bc3 ----
    if (t < 10) {
        const float* __restrict__ w3 = Wc3 + t;
        float o0 = 0.0f, o1 = 0.0f, o2 = 0.0f, o3 = 0.0f;
#pragma unroll
        for (int k = 0; k < 128; k += 4) {
            o0 = fmaf(sh2[k + 0], w3[(k + 0) * 10], o0);
            o1 = fmaf(sh2[k + 1], w3[(k + 1) * 10], o1);
            o2 = fmaf(sh2[k + 2], w3[(k + 2) * 10], o2);
            o3 = fmaf(sh2[k + 3], w3[(k + 3) * 10], o3);
        }
        out[b * 10 + t] = (o0 + o1) + (o2 + o3) + bc3[t];
    }
    __syncthreads();

    // Replay-state reset: last MLP block zeroes the counters.
    if (t == 0) {
        __threadfence();
        int old = atomicAdd(&g_ack, 1);
        if (old == NB - 1) {
            atomicExch(&g_done, 0);
            atomicExch(&g_ack, 0);
        }
    }
}

extern "C" void kernel_launch(void* const* d_in, const int* in_sizes, int n_in,
                              void* d_out, int out_size) {
    // metadata order: 0 h_comp  1 h_port  2 h_net | 3..6 edges (dead)
    // 7..9 gid_{comp,port,net} | 10..21 conv weights (dead)
    // 22 Wc1 23 bc1 24 Wc2 25 bc2 26 Wc3 27 bc3
    const float* h_comp  = (const float*)d_in[0];
    const float* h_port  = (const float*)d_in[1];
    const float* h_net   = (const float*)d_in[2];
    const int* gid_comp  = (const int*)d_in[7];
    const int* gid_port  = (const int*)d_in[8];
    const int* gid_net   = (const int*)d_in[9];
    const float* Wc1 = (const float*)d_in[22];
    const float* bc1 = (const float*)d_in[23];
    const float* Wc2 = (const float*)d_in[24];
    const float* bc2 = (const float*)d_in[25];
    const float* Wc3 = (const float*)d_in[26];
    const float* bc3 = (const float*)d_in[27];
    float* out = (float*)d_out;

    const int nc = in_sizes[0];
    const int np = in_sizes[1] / 2;
    const int nn = in_sizes[2];

    hx_fused_kernel<<<NBLK, 256>>>(h_comp, gid_comp, nc,
                                   h_port, gid_port, np,
                                   h_net,  gid_net,  nn,
                                   Wc1, bc1, Wc2, bc2, Wc3, bc3, out);
}

// round 14
// speedup vs baseline: 1.0015x; 1.0015x over previous
#include <cuda_runtime.h>

// ---------------------------------------------------------------------------
// ClassifierHetero — live dataflow only (conv stack is dead code in reference):
//   hg[b] = [mean(h_comp|g=b), mean2(h_port|g=b), mean(h_net|g=b)]  -> [64,4]
//   out   = relu(relu(hg@Wc1+bc1)@Wc2+bc2)@Wc3+bc3                  -> [64,10]
//
// R12: two-kernel structure (fused spin-barrier versions measured slower).
//  - Reduce: sorted-gid trick — window uniform iff gid[base]==gid[base+127];
//    2 broadcast gid probes replace 512B of gid loads per 128-elem window.
//  - MLP: split-k Wc2 across 256 threads; Wc3 as one parallel load epoch +
//    smem/warp-shuffle reduction (kills the 5-epoch strided-load chain).
// ---------------------------------------------------------------------------

#define NB 64  // graphs

// Zero at load; MLP kernel consumes + resets (one consumer block per entry),
// so the zero-invariant holds across graph replays.
__device__ float g_sum[4 * NB];  // [0]=comp, [1]=port.x, [2]=port.y, [3]=net
__device__ int   g_cnt[3 * NB];  // [0]=comp, [1]=port,   [2]=net

__device__ __forceinline__ float warp_sum_f(float v) {
#pragma unroll
    for (int o = 16; o; o >>= 1) v += __shfl_xor_sync(0xffffffffu, v, o);
    return v;
}

// ---------------------------------------------------------------------------
// Reduce: 128-element warp windows. Sorted gids -> uniformity decided by the
// two endpoint gids (scalar broadcast loads). No ballots, no per-lane gids on
// the fast path.
// ---------------------------------------------------------------------------
__global__ void hx_reduce_kernel(const float* __restrict__ h_comp,
                                 const int*   __restrict__ gid_comp, int nc,
                                 const float* __restrict__ h_port,
                                 const int*   __restrict__ gid_port, int np,
                                 const float* __restrict__ h_net,
                                 const int*   __restrict__ gid_net,  int nn) {
    __shared__ float s_sum[4 * NB];
    __shared__ int   s_cnt[3 * NB];
    for (int i = threadIdx.x; i < 4 * NB; i += blockDim.x) s_sum[i] = 0.0f;
    for (int i = threadIdx.x; i < 3 * NB; i += blockDim.x) s_cnt[i] = 0;
    __syncthreads();

    const int lane   = threadIdx.x & 31;
    const int warp_g = (blockIdx.x * blockDim.x + threadIdx.x) >> 5;
    const int nwarps = (gridDim.x * blockDim.x) >> 5;

    const int wc_c = (nc + 127) >> 7;
    const int wc_p = (np + 127) >> 7;
    const int wc_n = (nn + 127) >> 7;
    const int wc_total = wc_c + wc_p + wc_n;

    for (int w = warp_g; w < wc_total; w += nwarps) {
        if (w < wc_c) {
            // ---- component: 1 column ----
            int base = w << 7;
            if (base + 128 <= nc) {
                int ga = __ldg(gid_comp + base);
                int gb = __ldg(gid_comp + base + 127);
                float4 v4 = *reinterpret_cast<const float4*>(h_comp + base + lane * 4);
                if (ga == gb) {
                    float s = warp_sum_f((v4.x + v4.y) + (v4.z + v4.w));
                    if (lane == 0) {
                        atomicAdd(&s_sum[0 * NB + ga], s);
                        atomicAdd(&s_cnt[0 * NB + ga], 128);
                    }
                } else {  // boundary window (~rare): per-element
                    int4 g4 = *reinterpret_cast<const int4*>(gid_comp + base + lane * 4);
                    int   gg[4] = {g4.x, g4.y, g4.z, g4.w};
                    float vv[4] = {v4.x, v4.y, v4.z, v4.w};
#pragma unroll
                    for (int e = 0; e < 4; e++) {
                        atomicAdd(&s_sum[0 * NB + gg[e]], vv[e]);
                        atomicAdd(&s_cnt[0 * NB + gg[e]], 1);
                    }
                }
            } else {
#pragma unroll
                for (int e = 0; e < 4; e++) {
                    int id = base + lane * 4 + e;
                    if (id < nc) {
                        int g = gid_comp[id];
                        atomicAdd(&s_sum[0 * NB + g], h_comp[id]);
                        atomicAdd(&s_cnt[0 * NB + g], 1);
                    }
                }
            }
        } else if (w < wc_c + wc_p) {
            // ---- port: 2 columns ----
            int base = (w - wc_c) << 7;
            if (base + 128 <= np) {
                int ga = __ldg(gid_port + base);
                int gb = __ldg(gid_port + base + 127);
                int idx = base + lane * 4;
                float4 lo = *reinterpret_cast<const float4*>(h_port + 2 * idx);
                float4 hi = *reinterpret_cast<const float4*>(h_port + 2 * idx + 4);
                if (ga == gb) {
                    float sx = warp_sum_f((lo.x + lo.z) + (hi.x + hi.z));
                    float sy = warp_sum_f((lo.y + lo.w) + (hi.y + hi.w));
                    if (lane == 0) {
                        atomicAdd(&s_sum[1 * NB + ga], sx);
                        atomicAdd(&s_sum[2 * NB + ga], sy);
                        atomicAdd(&s_cnt[1 * NB + ga], 128);
                    }
                } else {
                    int4 g4 = *reinterpret_cast<const int4*>(gid_port + idx);
                    int   gg[4] = {g4.x, g4.y, g4.z, g4.w};
                    float vx[4] = {lo.x, lo.z, hi.x, hi.z};
                    float vy[4] = {lo.y, lo.w, hi.y, hi.w};
#pragma unroll
                    for (int e = 0; e < 4; e++) {
                        atomicAdd(&s_sum[1 * NB + gg[e]], vx[e]);
                        atomicAdd(&s_sum[2 * NB + gg[e]], vy[e]);
                        atomicAdd(&s_cnt[1 * NB + gg[e]], 1);
                    }
                }
            } else {
#pragma unroll
                for (int e = 0; e < 4; e++) {
                    int id = base + lane * 4 + e;
                    if (id < np) {
                        int g = gid_port[id];
                        float2 v = reinterpret_cast<const float2*>(h_port)[id];
                        atomicAdd(&s_sum[1 * NB + g], v.x);
                        atomicAdd(&s_sum[2 * NB + g], v.y);
                        atomicAdd(&s_cnt[1 * NB + g], 1);
                    }
                }
            }
        } else {
            // ---- net: 1 column ----
            int base = (w - wc_c - wc_p) << 7;
            if (base + 128 <= nn) {
                int ga = __ldg(gid_net + base);
                int gb = __ldg(gid_net + base + 127);
                float4 v4 = *reinterpret_cast<const float4*>(h_net + base + lane * 4);
                if (ga == gb) {
                    float s = warp_sum_f((v4.x + v4.y) + (v4.z + v4.w));
                    if (lane == 0) {
                        atomicAdd(&s_sum[3 * NB + ga], s);
                        atomicAdd(&s_cnt[2 * NB + ga], 128);
                    }
                } else {
                    int4 g4 = *reinterpret_cast<const int4*>(gid_net + base + lane * 4);
                    int   gg[4] = {g4.x, g4.y, g4.z, g4.w};
                    float vv[4] = {v4.x, v4.y, v4.z, v4.w};
#pragma unroll
                    for (int e = 0; e < 4; e++) {
                        atomicAdd(&s_sum[3 * NB + gg[e]], vv[e]);
                        atomicAdd(&s_cnt[2 * NB + gg[e]], 1);
                    }
                }
            } else {
#pragma unroll
                for (int e = 0; e < 4; e++) {
                    int id = base + lane * 4 + e;
                    if (id < nn) {
                        int g = gid_net[id];
                        atomicAdd(&s_sum[3 * NB + g], h_net[id]);
                        atomicAdd(&s_cnt[2 * NB + g], 1);
                    }
                }
            }
        }
    }
    __syncthreads();

    // Sorted gids -> few nonzero bins per block; flush those only.
    for (int i = threadIdx.x; i < 4 * NB; i += blockDim.x)
        if (s_sum[i] != 0.0f) atomicAdd(&g_sum[i], s_sum[i]);
    for (int i = threadIdx.x; i < 3 * NB; i += blockDim.x)
        if (s_cnt[i] != 0) atomicAdd(&g_cnt[i], s_cnt[i]);
}

// ---------------------------------------------------------------------------
// MLP: one block of 256 threads per graph row. Consumes + resets accumulators.
//  - Wc2 dot: split-k by 2 (64 unrolled loads/thread, combined via smem)
//  - Wc3 dot: thread k loads its 10-float Wc3 row (one epoch), writes partial
//    products to smem; 8 warps shuffle-reduce the 10 outputs.
// ---------------------------------------------------------------------------
__global__ void hx_mlp_kernel(const float* __restrict__ Wc1, const float* __restrict__ bc1,
                              const float* __restrict__ Wc2, const float* __restrict__ bc2,
                              const float* __restrict__ Wc3, const float* __restrict__ bc3,
                              float* __restrict__ out) {
    const int b = blockIdx.x;
    const int t = threadIdx.x;   // 0..255
    const int j = t & 127;
    const int h = t >> 7;
    const int lane = t & 31;
    const int warp = t >> 5;

    __shared__ float shg[4];
    __shared__ float sh1[128];
    __shared__ float s_part[256];
    __shared__ float sh2[128];
    __shared__ float s_p3[10 * 128];

    if (t == 0) {
        float s0 = __ldcg(&g_sum[0 * NB + b]);
        float s1 = __ldcg(&g_sum[1 * NB + b]);
        float s2 = __ldcg(&g_sum[2 * NB + b]);
        float s3 = __ldcg(&g_sum[3 * NB + b]);
        float c0 = (float)__ldcg(&g_cnt[0 * NB + b]);
        float c1 = (float)__ldcg(&g_cnt[1 * NB + b]);
        float c2 = (float)__ldcg(&g_cnt[2 * NB + b]);
        shg[0] = s0 / fmaxf(c0, 1.0f);
        shg[1] = s1 / fmaxf(c1, 1.0f);
        shg[2] = s2 / fmaxf(c1, 1.0f);
        shg[3] = s3 / fmaxf(c2, 1.0f);
        g_sum[0 * NB + b] = 0.0f;
        g_sum[1 * NB + b] = 0.0f;
        g_sum[2 * NB + b] = 0.0f;
        g_sum[3 * NB + b] = 0.0f;
        g_cnt[0 * NB + b] = 0;
        g_cnt[1 * NB + b] = 0;
        g_cnt[2 * NB + b] = 0;
    }
    __syncthreads();

    // ---- h1 = relu(hg @ Wc1 + bc1) ----
    if (t < 128) {
        float v = shg[0] * Wc1[0 * 128 + j] + shg[1] * Wc1[1 * 128 + j] +
                  shg[2] * Wc1[2 * 128 + j] + shg[3] * Wc1[3 * 128 + j] + bc1[j];
        sh1[j] = fmaxf(v, 0.0f);
    }
    __syncthreads();

    // ---- h2 = relu(sh1 @ Wc2 + bc2): split-k by 2 ----
    {
        const float* __restrict__ w2 = Wc2 + (h * 64) * 128 + j;
        const float* __restrict__ x1 = sh1 + h * 64;
        float a0 = 0.0f, a1 = 0.0f, a2 = 0.0f, a3 = 0.0f;
#pragma unroll
        for (int k = 0; k < 64; k += 4) {
            a0 = fmaf(x1[k + 0], w2[(k + 0) * 128], a0);
            a1 = fmaf(x1[k + 1], w2[(k + 1) * 128], a1);
            a2 = fmaf(x1[k + 2], w2[(k + 2) * 128], a2);
            a3 = fmaf(x1[k + 3], w2[(k + 3) * 128], a3);
        }
        s_part[t] = (a0 + a1) + (a2 + a3);
    }
    __syncthreads();
    if (t < 128)
        sh2[j] = fmaxf(s_part[j] + s_part[128 + j] + bc2[j], 0.0f);
    __syncthreads();

    // ---- out = sh2 @ Wc3 + bc3: one parallel load epoch + warp reduction ----
    if (t < 128) {
        const float xv = sh2[t];
        const float* __restrict__ w3 = Wc3 + t * 10;
#pragma unroll
        for (int o = 0; o < 10; o++)
            s_p3[o * 128 + t] = xv * __ldg(w3 + o);
    }
    __syncthreads();
    // warp w handles outputs w and w+8 (10 outputs over 8 warps)
    for (int o = warp; o < 10; o += 8) {
        const float* p = s_p3 + o * 128;
        float v = p[lane] + p[lane + 32] + p[lane + 64] + p[lane + 96];
        v = warp_sum_f(v);
        if (lane == 0) out[b * 10 + o] = v + bc3[o];
    }
}

extern "C" void kernel_launch(void* const* d_in, const int* in_sizes, int n_in,
                              void* d_out, int out_size) {
    // metadata order: 0 h_comp  1 h_port  2 h_net | 3..6 edges (dead)
    // 7..9 gid_{comp,port,net} | 10..21 conv weights (dead)
    // 22 Wc1 23 bc1 24 Wc2 25 bc2 26 Wc3 27 bc3
    const float* h_comp  = (const float*)d_in[0];
    const float* h_port  = (const float*)d_in[1];
    const float* h_net   = (const float*)d_in[2];
    const int* gid_comp  = (const int*)d_in[7];
    const int* gid_port  = (const int*)d_in[8];
    const int* gid_net   = (const int*)d_in[9];
    const float* Wc1 = (const float*)d_in[22];
    const float* bc1 = (const float*)d_in[23];
    const float* Wc2 = (const float*)d_in[24];
    const float* bc2 = (const float*)d_in[25];
    const float* Wc3 = (const float*)d_in[26];
    const float* bc3 = (const float*)d_in[27];
    float* out = (float*)d_out;

    const int nc = in_sizes[0];
    const int np = in_sizes[1] / 2;
    const int nn = in_sizes[2];

    hx_reduce_kernel<<<592, 256>>>(h_comp, gid_comp, nc,
                                   h_port, gid_port, np,
                                   h_net,  gid_net,  nn);
    hx_mlp_kernel<<<NB, 256>>>(Wc1, bc1, Wc2, bc2, Wc3, bc3, out);
}